// round 15
// baseline (speedup 1.0000x reference)
#include <cuda_runtime.h>
#include <math.h>
#include <stdint.h>

// Problem constants
#define NB   2
#define TT   1024
#define DD   1024
#define HH   16
#define DHH  64
#define WW   64
#define WIN  129

// GEMM dims
#define GM 2048
#define GN 1024
#define GK 1024
// Tiling (R10 verified)
#define BM 128
#define BN 128
#define BK 32
#define SROW 36
#define NITER (GK / BK)

// Attention tiling (R13 verified)
#define AR   32
#define AU   160
#define AQS  68
#define AKS  68
#define APS  164
#define AVTS 164
#define SM_Q   0
#define SM_K   2176
#define SM_VT  13056
#define SM_RED 23552
#define SM_INV 23712
#define ATT_SMEM_FLOATS 23744

#define FUSED_SMEM_BYTES (ATT_SMEM_FLOATS * 4)   // 94976 >= 73728 (gemm need)

#define N_QKV  384
#define N_ATT  1024
#define N_OUT  128
#define GRID_P 296      // 2 CTAs/SM x 148 SMs (correctness does NOT depend on this)

// Scratch (device globals: allocation-free per harness rules)
__device__ float g_q[NB * TT * DD];
__device__ float g_k[NB * TT * DD];
__device__ float g_v[NB * TT * DD];
__device__ float g_attn[NB * TT * DD];
__device__ int   g_flags[384];     // [z][my][nx] = z*128 + my*8 + nx
__device__ int   g_rowcnt[16];     // per 128-row group of attn output
__device__ int   g_ctr[3];         // qkv / attn / out queue heads

__device__ __forceinline__ float to_tf32(float x) {
    float r;
    asm("cvt.rna.tf32.f32 %0, %1;" : "=f"(r) : "f"(x));
    return r;
}

__device__ __forceinline__ void mma_16x8x8_tf32(float* d, const uint32_t* a,
                                                const uint32_t* b) {
    asm volatile(
        "mma.sync.aligned.m16n8k8.row.col.f32.tf32.tf32.f32 "
        "{%0,%1,%2,%3}, {%4,%5,%6,%7}, {%8,%9}, {%0,%1,%2,%3};"
        : "+f"(d[0]), "+f"(d[1]), "+f"(d[2]), "+f"(d[3])
        : "r"(a[0]), "r"(a[1]), "r"(a[2]), "r"(a[3]),
          "r"(b[0]), "r"(b[1]));
}

__device__ __forceinline__ void spin_flag(int* f) {
    while (atomicAdd(f, 0) == 0) __nanosleep(64);
}

// ---------------------------------------------------------------------------
// tf32 mma.sync GEMM tile body (R10 verbatim, parameterized by tile coords)
// ---------------------------------------------------------------------------
__device__ __forceinline__ void gemm_tc_body(
    const float* __restrict__ A, const float* __restrict__ B,
    const float* __restrict__ bias, float* __restrict__ C,
    int row0, int col0)
{
    extern __shared__ float smem[];
    float* Asm = smem;
    float* Bsm = smem + 2 * BM * SROW;

    const int tid  = threadIdx.x;
    const int lane = tid & 31;
    const int wid  = tid >> 5;
    const int wm   = wid >> 2;
    const int wn   = wid & 3;

    const int lrow = tid >> 3;
    const int lq   = tid & 7;

    float acc[4][4][4];
#pragma unroll
    for (int m = 0; m < 4; ++m)
#pragma unroll
        for (int n = 0; n < 4; ++n)
#pragma unroll
            for (int e = 0; e < 4; ++e) acc[m][n][e] = 0.f;

    float4 pa[4], pb[4];

#pragma unroll
    for (int p = 0; p < 4; ++p) {
        int r = p * 32 + lrow;
        pa[p] = *(const float4*)(A + (size_t)(row0 + r) * GK + lq * 4);
        pb[p] = *(const float4*)(B + (size_t)(col0 + r) * GK + lq * 4);
    }
#pragma unroll
    for (int p = 0; p < 4; ++p) {
        int r = p * 32 + lrow;
        float4 va = pa[p], vb = pb[p];
        va.x = to_tf32(va.x); va.y = to_tf32(va.y);
        va.z = to_tf32(va.z); va.w = to_tf32(va.w);
        vb.x = to_tf32(vb.x); vb.y = to_tf32(vb.y);
        vb.z = to_tf32(vb.z); vb.w = to_tf32(vb.w);
        *(float4*)(Asm + r * SROW + lq * 4) = va;
        *(float4*)(Bsm + r * SROW + lq * 4) = vb;
    }
    __syncthreads();

    const int c  = lane & 3;
    const int r4 = lane >> 2;

    for (int i = 0; i < NITER; ++i) {
        const int buf = i & 1;
        const float* Ab = Asm + buf * (BM * SROW);
        const float* Bb = Bsm + buf * (BM * SROW);

        if (i + 1 < NITER) {
            const int k0 = (i + 1) * BK;
#pragma unroll
            for (int p = 0; p < 4; ++p) {
                int r = p * 32 + lrow;
                pa[p] = *(const float4*)(A + (size_t)(row0 + r) * GK + k0 + lq * 4);
                pb[p] = *(const float4*)(B + (size_t)(col0 + r) * GK + k0 + lq * 4);
            }
        }

        const uint32_t* Au = (const uint32_t*)(Ab + (wm * 64 + r4) * SROW + c);
        const uint32_t* Bu = (const uint32_t*)(Bb + (wn * 32 + r4) * SROW + c);

#pragma unroll
        for (int kk = 0; kk < 4; ++kk) {
            uint32_t af[4][4], bf[4][2];
            const int ko = kk * 8;
#pragma unroll
            for (int m = 0; m < 4; ++m) {
                af[m][0] = Au[(m * 16 + 0) * SROW + ko + 0];
                af[m][1] = Au[(m * 16 + 8) * SROW + ko + 0];
                af[m][2] = Au[(m * 16 + 0) * SROW + ko + 4];
                af[m][3] = Au[(m * 16 + 8) * SROW + ko + 4];
            }
#pragma unroll
            for (int n = 0; n < 4; ++n) {
                bf[n][0] = Bu[n * 8 * SROW + ko + 0];
                bf[n][1] = Bu[n * 8 * SROW + ko + 4];
            }
#pragma unroll
            for (int m = 0; m < 4; ++m)
#pragma unroll
                for (int n = 0; n < 4; ++n)
                    mma_16x8x8_tf32(acc[m][n], af[m], bf[n]);
        }

        if (i + 1 < NITER) {
            float* Aw = Asm + (buf ^ 1) * (BM * SROW);
            float* Bw = Bsm + (buf ^ 1) * (BM * SROW);
#pragma unroll
            for (int p = 0; p < 4; ++p) {
                int r = p * 32 + lrow;
                float4 va = pa[p], vb = pb[p];
                va.x = to_tf32(va.x); va.y = to_tf32(va.y);
                va.z = to_tf32(va.z); va.w = to_tf32(va.w);
                vb.x = to_tf32(vb.x); vb.y = to_tf32(vb.y);
                vb.z = to_tf32(vb.z); vb.w = to_tf32(vb.w);
                *(float4*)(Aw + r * SROW + lq * 4) = va;
                *(float4*)(Bw + r * SROW + lq * 4) = vb;
            }
            __syncthreads();
        }
    }

#pragma unroll
    for (int m = 0; m < 4; ++m) {
#pragma unroll
        for (int h = 0; h < 2; ++h) {
            const int grow = row0 + wm * 64 + m * 16 + r4 + 8 * h;
            float* crow = C + (size_t)grow * GN;
#pragma unroll
            for (int n = 0; n < 4; ++n) {
                const int gcol = col0 + wn * 32 + n * 8 + 2 * c;
                float2 o;
                o.x = acc[m][n][2 * h + 0] + __ldg(&bias[gcol + 0]);
                o.y = acc[m][n][2 * h + 1] + __ldg(&bias[gcol + 1]);
                *(float2*)(crow + gcol) = o;
            }
        }
    }
}

// ---------------------------------------------------------------------------
// Attention tile body (R13 verbatim, parameterized by (tb, nh))
// ---------------------------------------------------------------------------
__device__ __forceinline__ void attn_body(int tb, int nh)
{
    extern __shared__ float sm[];
    float* Qs   = sm + SM_Q;
    float* Ks   = sm + SM_K;
    float* Vt   = sm + SM_VT;
    float* red  = sm + SM_RED;
    float* rinv = sm + SM_INV;

    const int tid = threadIdx.x;
    const int t0  = tb * AR;
    const int h   = nh & (HH - 1);
    const int n   = nh >> 4;
    const size_t base = (size_t)n * TT * DD + (size_t)h * DHH;

    for (int idx = tid; idx < AR * 16; idx += 256) {
        int r = idx >> 4, cc = (idx & 15) << 2;
        float4 v = *(const float4*)(g_q + base + (size_t)(t0 + r) * DD + cc);
        v.x = to_tf32(v.x * 0.125f); v.y = to_tf32(v.y * 0.125f);
        v.z = to_tf32(v.z * 0.125f); v.w = to_tf32(v.w * 0.125f);
        *(float4*)(Qs + r * AQS + cc) = v;
    }
    for (int idx = tid; idx < AU * 16; idx += 256) {
        int r = idx >> 4, cc = (idx & 15) << 2;
        int pos = min(max(t0 - 64 + r, 0), TT - 1);
        float4 kv = *(const float4*)(g_k + base + (size_t)pos * DD + cc);
        kv.x = to_tf32(kv.x); kv.y = to_tf32(kv.y);
        kv.z = to_tf32(kv.z); kv.w = to_tf32(kv.w);
        *(float4*)(Ks + r * AKS + cc) = kv;
    }
    {
        const int dh   = tid & 63;
        const int pgrp = tid >> 6;
        const float* vg = g_v + base + dh;
#pragma unroll
        for (int l = 0; l < 10; ++l) {
            int p0 = l * 16 + pgrp * 4;
            float4 vv;
            int q0 = min(max(t0 - 64 + p0 + 0, 0), TT - 1);
            int q1 = min(max(t0 - 64 + p0 + 1, 0), TT - 1);
            int q2 = min(max(t0 - 64 + p0 + 2, 0), TT - 1);
            int q3 = min(max(t0 - 64 + p0 + 3, 0), TT - 1);
            vv.x = to_tf32(vg[(size_t)q0 * DD]);
            vv.y = to_tf32(vg[(size_t)q1 * DD]);
            vv.z = to_tf32(vg[(size_t)q2 * DD]);
            vv.w = to_tf32(vg[(size_t)q3 * DD]);
            *(float4*)(Vt + dh * AVTS + p0) = vv;
        }
    }
    __syncthreads();

    const int lane = tid & 31, wid = tid >> 5;
    const int r4  = lane >> 2;
    const int cfr = lane & 3;
    const int mtile = wid & 1;
    const int wg    = wid >> 1;

    float acc[5][4];
#pragma unroll
    for (int nt = 0; nt < 5; ++nt)
#pragma unroll
        for (int e = 0; e < 4; ++e) acc[nt][e] = 0.f;

    const uint32_t* Aq = (const uint32_t*)(Qs + (mtile * 16 + r4) * AQS + cfr);
    const uint32_t* Bk = (const uint32_t*)(Ks + (wg * 40 + r4) * AKS + cfr);
#pragma unroll
    for (int ks = 0; ks < 8; ++ks) {
        const int ko = ks * 8;
        uint32_t af[4];
        af[0] = Aq[ko];
        af[1] = Aq[8 * AQS + ko];
        af[2] = Aq[ko + 4];
        af[3] = Aq[8 * AQS + ko + 4];
#pragma unroll
        for (int nt = 0; nt < 5; ++nt) {
            uint32_t bf[2];
            bf[0] = Bk[nt * 8 * AKS + ko];
            bf[1] = Bk[nt * 8 * AKS + ko + 4];
            mma_16x8x8_tf32(acc[nt], af, bf);
        }
    }

    const int lob = 64 - t0;
    const int hib = 1087 - t0;
    const int row0g = mtile * 16 + r4;
    const int lo0 = max(row0g, lob),     hi0 = min(row0g + 128, hib);
    const int lo1 = max(row0g + 8, lob), hi1 = min(row0g + 136, hib);

    float m0 = -1e30f, m1 = -1e30f;
#pragma unroll
    for (int nt = 0; nt < 5; ++nt) {
#pragma unroll
        for (int e = 0; e < 2; ++e) {
            int col = wg * 40 + nt * 8 + 2 * cfr + e;
            if (col < lo0 || col > hi0) acc[nt][e] = -1e30f;
            m0 = fmaxf(m0, acc[nt][e]);
            if (col < lo1 || col > hi1) acc[nt][2 + e] = -1e30f;
            m1 = fmaxf(m1, acc[nt][2 + e]);
        }
    }
    m0 = fmaxf(m0, __shfl_xor_sync(0xffffffffu, m0, 1));
    m0 = fmaxf(m0, __shfl_xor_sync(0xffffffffu, m0, 2));
    m1 = fmaxf(m1, __shfl_xor_sync(0xffffffffu, m1, 1));
    m1 = fmaxf(m1, __shfl_xor_sync(0xffffffffu, m1, 2));
    if (cfr == 0) {
        red[(row0g + 0) * 5 + wg] = m0;
        red[(row0g + 8) * 5 + wg] = m1;
    }
    __syncthreads();
    {
        const float* q0 = red + (row0g + 0) * 5;
        const float* q1 = red + (row0g + 8) * 5;
        m0 = fmaxf(fmaxf(q0[0], q0[1]), fmaxf(q0[2], q0[3]));
        m1 = fmaxf(fmaxf(q1[0], q1[1]), fmaxf(q1[2], q1[3]));
    }
    __syncthreads();

    float* Ps = Ks;
    float s0 = 0.f, s1 = 0.f;
    float* P0 = Ps + (row0g + 0) * APS + wg * 40 + 2 * cfr;
    float* P1 = Ps + (row0g + 8) * APS + wg * 40 + 2 * cfr;
#pragma unroll
    for (int nt = 0; nt < 5; ++nt) {
        float e0 = to_tf32(__expf(acc[nt][0] - m0));
        float e1 = to_tf32(__expf(acc[nt][1] - m0));
        s0 += e0 + e1;
        *(float2*)(P0 + nt * 8) = make_float2(e0, e1);
        float e2 = to_tf32(__expf(acc[nt][2] - m1));
        float e3 = to_tf32(__expf(acc[nt][3] - m1));
        s1 += e2 + e3;
        *(float2*)(P1 + nt * 8) = make_float2(e2, e3);
    }
    s0 += __shfl_xor_sync(0xffffffffu, s0, 1);
    s0 += __shfl_xor_sync(0xffffffffu, s0, 2);
    s1 += __shfl_xor_sync(0xffffffffu, s1, 1);
    s1 += __shfl_xor_sync(0xffffffffu, s1, 2);
    if (cfr == 0) {
        red[(row0g + 0) * 5 + wg] = s0;
        red[(row0g + 8) * 5 + wg] = s1;
    }
    __syncthreads();
    if (tid < AR) {
        const float* q = red + tid * 5;
        rinv[tid] = 1.0f / (q[0] + q[1] + q[2] + q[3]);
    }
    __syncthreads();

    const int nbase = (wid >> 1) * 16;
    float pv[2][4];
#pragma unroll
    for (int nt = 0; nt < 2; ++nt)
#pragma unroll
        for (int e = 0; e < 4; ++e) pv[nt][e] = 0.f;

    const uint32_t* Pa  = (const uint32_t*)(Ps + (mtile * 16 + r4) * APS + cfr);
    const uint32_t* Vb0 = (const uint32_t*)(Vt + (nbase + 0 + r4) * AVTS + cfr);
    const uint32_t* Vb1 = (const uint32_t*)(Vt + (nbase + 8 + r4) * AVTS + cfr);
#pragma unroll
    for (int ks = 0; ks < 20; ++ks) {
        const int kc = ks * 8;
        uint32_t af[4];
        af[0] = Pa[kc];
        af[1] = Pa[8 * APS + kc];
        af[2] = Pa[kc + 4];
        af[3] = Pa[8 * APS + kc + 4];
        uint32_t b0[2] = { Vb0[kc], Vb0[kc + 4] };
        uint32_t b1[2] = { Vb1[kc], Vb1[kc + 4] };
        mma_16x8x8_tf32(pv[0], af, b0);
        mma_16x8x8_tf32(pv[1], af, b1);
    }

    const float i0 = rinv[row0g];
    const float i1 = rinv[row0g + 8];
    float* orow0 = g_attn + base + (size_t)(t0 + row0g + 0) * DD;
    float* orow1 = g_attn + base + (size_t)(t0 + row0g + 8) * DD;
#pragma unroll
    for (int nt = 0; nt < 2; ++nt) {
        const int col = nbase + nt * 8 + 2 * cfr;
        *(float2*)(orow0 + col) = make_float2(pv[nt][0] * i0, pv[nt][1] * i0);
        *(float2*)(orow1 + col) = make_float2(pv[nt][2] * i1, pv[nt][3] * i1);
    }
}

// ---------------------------------------------------------------------------
// Reset flags/counters (runs before each fused launch, incl. graph replays)
// ---------------------------------------------------------------------------
__global__ void reset_kernel()
{
    int t = threadIdx.x;
    if (t < 384) g_flags[t] = 0;
    if (t < 16)  g_rowcnt[t] = 0;
    if (t < 3)   g_ctr[t] = 0;
}

// ---------------------------------------------------------------------------
// Persistent fused kernel with work queues. Deadlock-free by construction:
// a CTA enters phase P+1 only after phase P's queue is fully CLAIMED, and
// claimed work is running on a CTA at-or-before its own phase (never blocked
// on later-phase work). Holds for ANY dispatch order / residency.
// ---------------------------------------------------------------------------
__global__ __launch_bounds__(256, 2) void fused_kernel(
    const float* __restrict__ x,
    const float* __restrict__ wq, const float* __restrict__ bq,
    const float* __restrict__ wk, const float* __restrict__ bk,
    const float* __restrict__ wv, const float* __restrict__ bv,
    const float* __restrict__ wo, const float* __restrict__ bo,
    float* __restrict__ out)
{
    __shared__ int s_task;
    const int tid = threadIdx.x;

    // ---- phase 1: QKV tiles (my-major so early row-groups finish first) ----
    for (;;) {
        __syncthreads();
        if (tid == 0) s_task = atomicAdd(&g_ctr[0], 1);
        __syncthreads();
        const int t = s_task;
        if (t >= N_QKV) break;
        const int my = t / 24;
        const int z  = (t / 8) % 3;
        const int nx = t & 7;
        const float* B; const float* bias; float* C;
        if (z == 0)      { B = wq; bias = bq; C = g_q; }
        else if (z == 1) { B = wk; bias = bk; C = g_k; }
        else             { B = wv; bias = bv; C = g_v; }
        gemm_tc_body(x, B, bias, C, my * BM, nx * BN);
        __syncthreads();
        if (tid == 0) {
            __threadfence();
            atomicExch(&g_flags[z * 128 + my * 8 + nx], 1);
        }
    }

    // ---- phase 2: attention blocks (row-group-major) ----
    for (;;) {
        __syncthreads();
        if (tid == 0) s_task = atomicAdd(&g_ctr[1], 1);
        __syncthreads();
        const int a = s_task;
        if (a >= N_ATT) break;
        const int rg = a >> 6;               // output row-group 0..15
        const int j  = a & 63;
        const int n  = rg >> 3;
        const int tb = (rg & 7) * 4 + (j >> 4);
        const int h  = j & 15;
        const int nh = n * 16 + h;
        if (tid == 0) {
            const int nt  = h >> 1;          // 128-col tile containing head h
            const int lo  = max(32 * tb - 64, 0);
            const int hi  = min(32 * tb + 95, TT - 1);
            const int mlo = n * 8 + lo / 128;
            const int mhi = n * 8 + hi / 128;
            spin_flag(&g_flags[0 * 128 + rg  * 8 + nt]);
            spin_flag(&g_flags[1 * 128 + mlo * 8 + nt]);
            spin_flag(&g_flags[1 * 128 + mhi * 8 + nt]);
            spin_flag(&g_flags[2 * 128 + mlo * 8 + nt]);
            spin_flag(&g_flags[2 * 128 + mhi * 8 + nt]);
            __threadfence();
        }
        __syncthreads();
        attn_body(tb, nh);
        __syncthreads();
        if (tid == 0) {
            __threadfence();
            atomicAdd(&g_rowcnt[rg], 1);
        }
    }

    // ---- phase 3: out-projection tiles (my-major) ----
    for (;;) {
        __syncthreads();
        if (tid == 0) s_task = atomicAdd(&g_ctr[2], 1);
        __syncthreads();
        const int o = s_task;
        if (o >= N_OUT) break;
        const int my = o >> 3;
        const int nx = o & 7;
        if (tid == 0) {
            while (atomicAdd(&g_rowcnt[my], 0) < 64) __nanosleep(64);
            __threadfence();
        }
        __syncthreads();
        gemm_tc_body(g_attn, wo, bo, out, my * BM, nx * BN);
    }
}

// ---------------- launch ----------------
extern "C" void kernel_launch(void* const* d_in, const int* in_sizes, int n_in,
                              void* d_out, int out_size)
{
    const float* x  = (const float*)d_in[0];
    const float* wq = (const float*)d_in[1];
    const float* bq = (const float*)d_in[2];
    const float* wk = (const float*)d_in[3];
    const float* bk = (const float*)d_in[4];
    const float* wv = (const float*)d_in[5];
    const float* bv = (const float*)d_in[6];
    const float* wo = (const float*)d_in[7];
    const float* bo = (const float*)d_in[8];

    cudaFuncSetAttribute(fused_kernel,
                         cudaFuncAttributeMaxDynamicSharedMemorySize,
                         FUSED_SMEM_BYTES);

    reset_kernel<<<1, 512>>>();
    fused_kernel<<<GRID_P, 256, FUSED_SMEM_BYTES>>>(
        x, wq, bq, wk, bk, wv, bv, wo, bo, (float*)d_out);
}

// round 17
// speedup vs baseline: 1.0968x; 1.0968x over previous
#include <cuda_runtime.h>
#include <math.h>
#include <stdint.h>

// Problem constants
#define NB   2
#define TT   1024
#define DD   1024
#define HH   16
#define DHH  64
#define WW   64
#define WIN  129

// GEMM dims
#define GM 2048
#define GN 1024
#define GK 1024
// Tiling (R10 verified)
#define BM 128
#define BK 32
#define SROW 36
#define NITER (GK / BK)

// Attention tiling (R13 verified)
#define AR   32
#define AU   160
#define AQS  68
#define AKS  68
#define APS  164
#define AVTS 164
#define SM_Q   0
#define SM_K   2176
#define SM_VT  13056
#define SM_RED 23552
#define SM_INV 23712
#define ATT_SMEM_FLOATS 23744

#define FUSED_SMEM_BYTES (ATT_SMEM_FLOATS * 4)   // 94976 >= 73728 (gemm need)

#define N_QKV  384
#define N_ATT  1024
#define N_OUT  256      // out tiles are 128x64 -> 16 my x 16 nx
#define GRID_P 296

// Scratch (device globals: allocation-free per harness rules)
__device__ float g_q[NB * TT * DD];
__device__ float g_k[NB * TT * DD];
__device__ float g_v[NB * TT * DD];
__device__ float g_attn[NB * TT * DD];
__device__ int   g_flags[384];     // [z][my][nx] = z*128 + my*8 + nx
__device__ int   g_rowcnt[16];     // per 128-row group of attn output
__device__ int   g_ctr[3];         // qkv / attn / out queue heads

__device__ __forceinline__ float to_tf32(float x) {
    float r;
    asm("cvt.rna.tf32.f32 %0, %1;" : "=f"(r) : "f"(x));
    return r;
}

__device__ __forceinline__ void mma_16x8x8_tf32(float* d, const uint32_t* a,
                                                const uint32_t* b) {
    asm volatile(
        "mma.sync.aligned.m16n8k8.row.col.f32.tf32.tf32.f32 "
        "{%0,%1,%2,%3}, {%4,%5,%6,%7}, {%8,%9}, {%0,%1,%2,%3};"
        : "+f"(d[0]), "+f"(d[1]), "+f"(d[2]), "+f"(d[3])
        : "r"(a[0]), "r"(a[1]), "r"(a[2]), "r"(a[3]),
          "r"(b[0]), "r"(b[1]));
}

__device__ __forceinline__ void spin_flag(int* f) {
    while (atomicAdd(f, 0) == 0) __nanosleep(256);
}

// ---------------------------------------------------------------------------
// tf32 mma.sync GEMM tile body. NFR = warp n-fragment count; BN = NFR*32.
// NFR=4 reduces EXACTLY to the R10/R13-verified 128x128 body; NFR=2 is the
// 128x64 variant used only for the out-projection (smaller tail quantum).
// ---------------------------------------------------------------------------
template <int NFR>
__device__ __forceinline__ void gemm_tc_body(
    const float* __restrict__ A, const float* __restrict__ B,
    const float* __restrict__ bias, float* __restrict__ C,
    int row0, int col0)
{
    const int BNv = NFR * 32;
    extern __shared__ float smem[];
    float* Asm = smem;                         // [2][BM*SROW]
    float* Bsm = smem + 2 * BM * SROW;         // [2][BNv*SROW]

    const int tid  = threadIdx.x;
    const int lane = tid & 31;
    const int wid  = tid >> 5;
    const int wm   = wid >> 2;
    const int wn   = wid & 3;

    const int lrow = tid >> 3;
    const int lq   = tid & 7;

    float acc[4][NFR][4];
#pragma unroll
    for (int m = 0; m < 4; ++m)
#pragma unroll
        for (int n = 0; n < NFR; ++n)
#pragma unroll
            for (int e = 0; e < 4; ++e) acc[m][n][e] = 0.f;

    float4 pa[4], pb[NFR];

#pragma unroll
    for (int p = 0; p < 4; ++p) {
        int r = p * 32 + lrow;
        pa[p] = *(const float4*)(A + (size_t)(row0 + r) * GK + lq * 4);
    }
#pragma unroll
    for (int p = 0; p < NFR; ++p) {
        int r = p * 32 + lrow;
        pb[p] = *(const float4*)(B + (size_t)(col0 + r) * GK + lq * 4);
    }
#pragma unroll
    for (int p = 0; p < 4; ++p) {
        int r = p * 32 + lrow;
        float4 va = pa[p];
        va.x = to_tf32(va.x); va.y = to_tf32(va.y);
        va.z = to_tf32(va.z); va.w = to_tf32(va.w);
        *(float4*)(Asm + r * SROW + lq * 4) = va;
    }
#pragma unroll
    for (int p = 0; p < NFR; ++p) {
        int r = p * 32 + lrow;
        float4 vb = pb[p];
        vb.x = to_tf32(vb.x); vb.y = to_tf32(vb.y);
        vb.z = to_tf32(vb.z); vb.w = to_tf32(vb.w);
        *(float4*)(Bsm + r * SROW + lq * 4) = vb;
    }
    __syncthreads();

    const int c  = lane & 3;
    const int r4 = lane >> 2;

    for (int i = 0; i < NITER; ++i) {
        const int buf = i & 1;
        const float* Ab = Asm + buf * (BM * SROW);
        const float* Bb = Bsm + buf * (BNv * SROW);

        if (i + 1 < NITER) {
            const int k0 = (i + 1) * BK;
#pragma unroll
            for (int p = 0; p < 4; ++p) {
                int r = p * 32 + lrow;
                pa[p] = *(const float4*)(A + (size_t)(row0 + r) * GK + k0 + lq * 4);
            }
#pragma unroll
            for (int p = 0; p < NFR; ++p) {
                int r = p * 32 + lrow;
                pb[p] = *(const float4*)(B + (size_t)(col0 + r) * GK + k0 + lq * 4);
            }
        }

        const uint32_t* Au = (const uint32_t*)(Ab + (wm * 64 + r4) * SROW + c);
        const uint32_t* Bu = (const uint32_t*)(Bb + (wn * (NFR * 8) + r4) * SROW + c);

#pragma unroll
        for (int kk = 0; kk < 4; ++kk) {
            uint32_t af[4][4], bf[NFR][2];
            const int ko = kk * 8;
#pragma unroll
            for (int m = 0; m < 4; ++m) {
                af[m][0] = Au[(m * 16 + 0) * SROW + ko + 0];
                af[m][1] = Au[(m * 16 + 8) * SROW + ko + 0];
                af[m][2] = Au[(m * 16 + 0) * SROW + ko + 4];
                af[m][3] = Au[(m * 16 + 8) * SROW + ko + 4];
            }
#pragma unroll
            for (int n = 0; n < NFR; ++n) {
                bf[n][0] = Bu[n * 8 * SROW + ko + 0];
                bf[n][1] = Bu[n * 8 * SROW + ko + 4];
            }
#pragma unroll
            for (int m = 0; m < 4; ++m)
#pragma unroll
                for (int n = 0; n < NFR; ++n)
                    mma_16x8x8_tf32(acc[m][n], af[m], bf[n]);
        }

        if (i + 1 < NITER) {
            float* Aw = Asm + (buf ^ 1) * (BM * SROW);
            float* Bw = Bsm + (buf ^ 1) * (BNv * SROW);
#pragma unroll
            for (int p = 0; p < 4; ++p) {
                int r = p * 32 + lrow;
                float4 va = pa[p];
                va.x = to_tf32(va.x); va.y = to_tf32(va.y);
                va.z = to_tf32(va.z); va.w = to_tf32(va.w);
                *(float4*)(Aw + r * SROW + lq * 4) = va;
            }
#pragma unroll
            for (int p = 0; p < NFR; ++p) {
                int r = p * 32 + lrow;
                float4 vb = pb[p];
                vb.x = to_tf32(vb.x); vb.y = to_tf32(vb.y);
                vb.z = to_tf32(vb.z); vb.w = to_tf32(vb.w);
                *(float4*)(Bw + r * SROW + lq * 4) = vb;
            }
            __syncthreads();
        }
    }

#pragma unroll
    for (int m = 0; m < 4; ++m) {
#pragma unroll
        for (int h = 0; h < 2; ++h) {
            const int grow = row0 + wm * 64 + m * 16 + r4 + 8 * h;
            float* crow = C + (size_t)grow * GN;
#pragma unroll
            for (int n = 0; n < NFR; ++n) {
                const int gcol = col0 + wn * (NFR * 8) + n * 8 + 2 * c;
                float2 o;
                o.x = acc[m][n][2 * h + 0] + __ldg(&bias[gcol + 0]);
                o.y = acc[m][n][2 * h + 1] + __ldg(&bias[gcol + 1]);
                *(float2*)(crow + gcol) = o;
            }
        }
    }
}

// ---------------------------------------------------------------------------
// Attention tile body (R13 verbatim, parameterized by (tb, nh))
// ---------------------------------------------------------------------------
__device__ __forceinline__ void attn_body(int tb, int nh)
{
    extern __shared__ float sm[];
    float* Qs   = sm + SM_Q;
    float* Ks   = sm + SM_K;
    float* Vt   = sm + SM_VT;
    float* red  = sm + SM_RED;
    float* rinv = sm + SM_INV;

    const int tid = threadIdx.x;
    const int t0  = tb * AR;
    const int h   = nh & (HH - 1);
    const int n   = nh >> 4;
    const size_t base = (size_t)n * TT * DD + (size_t)h * DHH;

    for (int idx = tid; idx < AR * 16; idx += 256) {
        int r = idx >> 4, cc = (idx & 15) << 2;
        float4 v = *(const float4*)(g_q + base + (size_t)(t0 + r) * DD + cc);
        v.x = to_tf32(v.x * 0.125f); v.y = to_tf32(v.y * 0.125f);
        v.z = to_tf32(v.z * 0.125f); v.w = to_tf32(v.w * 0.125f);
        *(float4*)(Qs + r * AQS + cc) = v;
    }
    for (int idx = tid; idx < AU * 16; idx += 256) {
        int r = idx >> 4, cc = (idx & 15) << 2;
        int pos = min(max(t0 - 64 + r, 0), TT - 1);
        float4 kv = *(const float4*)(g_k + base + (size_t)pos * DD + cc);
        kv.x = to_tf32(kv.x); kv.y = to_tf32(kv.y);
        kv.z = to_tf32(kv.z); kv.w = to_tf32(kv.w);
        *(float4*)(Ks + r * AKS + cc) = kv;
    }
    {
        const int dh   = tid & 63;
        const int pgrp = tid >> 6;
        const float* vg = g_v + base + dh;
#pragma unroll
        for (int l = 0; l < 10; ++l) {
            int p0 = l * 16 + pgrp * 4;
            float4 vv;
            int q0 = min(max(t0 - 64 + p0 + 0, 0), TT - 1);
            int q1 = min(max(t0 - 64 + p0 + 1, 0), TT - 1);
            int q2 = min(max(t0 - 64 + p0 + 2, 0), TT - 1);
            int q3 = min(max(t0 - 64 + p0 + 3, 0), TT - 1);
            vv.x = to_tf32(vg[(size_t)q0 * DD]);
            vv.y = to_tf32(vg[(size_t)q1 * DD]);
            vv.z = to_tf32(vg[(size_t)q2 * DD]);
            vv.w = to_tf32(vg[(size_t)q3 * DD]);
            *(float4*)(Vt + dh * AVTS + p0) = vv;
        }
    }
    __syncthreads();

    const int lane = tid & 31, wid = tid >> 5;
    const int r4  = lane >> 2;
    const int cfr = lane & 3;
    const int mtile = wid & 1;
    const int wg    = wid >> 1;

    float acc[5][4];
#pragma unroll
    for (int nt = 0; nt < 5; ++nt)
#pragma unroll
        for (int e = 0; e < 4; ++e) acc[nt][e] = 0.f;

    const uint32_t* Aq = (const uint32_t*)(Qs + (mtile * 16 + r4) * AQS + cfr);
    const uint32_t* Bk = (const uint32_t*)(Ks + (wg * 40 + r4) * AKS + cfr);
#pragma unroll
    for (int ks = 0; ks < 8; ++ks) {
        const int ko = ks * 8;
        uint32_t af[4];
        af[0] = Aq[ko];
        af[1] = Aq[8 * AQS + ko];
        af[2] = Aq[ko + 4];
        af[3] = Aq[8 * AQS + ko + 4];
#pragma unroll
        for (int nt = 0; nt < 5; ++nt) {
            uint32_t bf[2];
            bf[0] = Bk[nt * 8 * AKS + ko];
            bf[1] = Bk[nt * 8 * AKS + ko + 4];
            mma_16x8x8_tf32(acc[nt], af, bf);
        }
    }

    const int lob = 64 - t0;
    const int hib = 1087 - t0;
    const int row0g = mtile * 16 + r4;
    const int lo0 = max(row0g, lob),     hi0 = min(row0g + 128, hib);
    const int lo1 = max(row0g + 8, lob), hi1 = min(row0g + 136, hib);

    float m0 = -1e30f, m1 = -1e30f;
#pragma unroll
    for (int nt = 0; nt < 5; ++nt) {
#pragma unroll
        for (int e = 0; e < 2; ++e) {
            int col = wg * 40 + nt * 8 + 2 * cfr + e;
            if (col < lo0 || col > hi0) acc[nt][e] = -1e30f;
            m0 = fmaxf(m0, acc[nt][e]);
            if (col < lo1 || col > hi1) acc[nt][2 + e] = -1e30f;
            m1 = fmaxf(m1, acc[nt][2 + e]);
        }
    }
    m0 = fmaxf(m0, __shfl_xor_sync(0xffffffffu, m0, 1));
    m0 = fmaxf(m0, __shfl_xor_sync(0xffffffffu, m0, 2));
    m1 = fmaxf(m1, __shfl_xor_sync(0xffffffffu, m1, 1));
    m1 = fmaxf(m1, __shfl_xor_sync(0xffffffffu, m1, 2));
    if (cfr == 0) {
        red[(row0g + 0) * 5 + wg] = m0;
        red[(row0g + 8) * 5 + wg] = m1;
    }
    __syncthreads();
    {
        const float* q0 = red + (row0g + 0) * 5;
        const float* q1 = red + (row0g + 8) * 5;
        m0 = fmaxf(fmaxf(q0[0], q0[1]), fmaxf(q0[2], q0[3]));
        m1 = fmaxf(fmaxf(q1[0], q1[1]), fmaxf(q1[2], q1[3]));
    }
    __syncthreads();

    float* Ps = Ks;
    float s0 = 0.f, s1 = 0.f;
    float* P0 = Ps + (row0g + 0) * APS + wg * 40 + 2 * cfr;
    float* P1 = Ps + (row0g + 8) * APS + wg * 40 + 2 * cfr;
#pragma unroll
    for (int nt = 0; nt < 5; ++nt) {
        float e0 = to_tf32(__expf(acc[nt][0] - m0));
        float e1 = to_tf32(__expf(acc[nt][1] - m0));
        s0 += e0 + e1;
        *(float2*)(P0 + nt * 8) = make_float2(e0, e1);
        float e2 = to_tf32(__expf(acc[nt][2] - m1));
        float e3 = to_tf32(__expf(acc[nt][3] - m1));
        s1 += e2 + e3;
        *(float2*)(P1 + nt * 8) = make_float2(e2, e3);
    }
    s0 += __shfl_xor_sync(0xffffffffu, s0, 1);
    s0 += __shfl_xor_sync(0xffffffffu, s0, 2);
    s1 += __shfl_xor_sync(0xffffffffu, s1, 1);
    s1 += __shfl_xor_sync(0xffffffffu, s1, 2);
    if (cfr == 0) {
        red[(row0g + 0) * 5 + wg] = s0;
        red[(row0g + 8) * 5 + wg] = s1;
    }
    __syncthreads();
    if (tid < AR) {
        const float* q = red + tid * 5;
        rinv[tid] = 1.0f / (q[0] + q[1] + q[2] + q[3]);
    }
    __syncthreads();

    const int nbase = (wid >> 1) * 16;
    float pv[2][4];
#pragma unroll
    for (int nt = 0; nt < 2; ++nt)
#pragma unroll
        for (int e = 0; e < 4; ++e) pv[nt][e] = 0.f;

    const uint32_t* Pa  = (const uint32_t*)(Ps + (mtile * 16 + r4) * APS + cfr);
    const uint32_t* Vb0 = (const uint32_t*)(Vt + (nbase + 0 + r4) * AVTS + cfr);
    const uint32_t* Vb1 = (const uint32_t*)(Vt + (nbase + 8 + r4) * AVTS + cfr);
#pragma unroll
    for (int ks = 0; ks < 20; ++ks) {
        const int kc = ks * 8;
        uint32_t af[4];
        af[0] = Pa[kc];
        af[1] = Pa[8 * APS + kc];
        af[2] = Pa[kc + 4];
        af[3] = Pa[8 * APS + kc + 4];
        uint32_t b0[2] = { Vb0[kc], Vb0[kc + 4] };
        uint32_t b1[2] = { Vb1[kc], Vb1[kc + 4] };
        mma_16x8x8_tf32(pv[0], af, b0);
        mma_16x8x8_tf32(pv[1], af, b1);
    }

    const float i0 = rinv[row0g];
    const float i1 = rinv[row0g + 8];
    float* orow0 = g_attn + base + (size_t)(t0 + row0g + 0) * DD;
    float* orow1 = g_attn + base + (size_t)(t0 + row0g + 8) * DD;
#pragma unroll
    for (int nt = 0; nt < 2; ++nt) {
        const int col = nbase + nt * 8 + 2 * cfr;
        *(float2*)(orow0 + col) = make_float2(pv[nt][0] * i0, pv[nt][1] * i0);
        *(float2*)(orow1 + col) = make_float2(pv[nt][2] * i1, pv[nt][3] * i1);
    }
}

// ---------------------------------------------------------------------------
// Reset flags/counters (runs before each fused launch, incl. graph replays)
// ---------------------------------------------------------------------------
__global__ void reset_kernel()
{
    int t = threadIdx.x;
    if (t < 384) g_flags[t] = 0;
    if (t < 16)  g_rowcnt[t] = 0;
    if (t < 3)   g_ctr[t] = 0;
}

// ---------------------------------------------------------------------------
// Persistent fused kernel (R15-verified skeleton; out tiles now 128x64 to
// shrink the critical-path tail quantum from 37us to ~18us).
// ---------------------------------------------------------------------------
__global__ __launch_bounds__(256, 2) void fused_kernel(
    const float* __restrict__ x,
    const float* __restrict__ wq, const float* __restrict__ bq,
    const float* __restrict__ wk, const float* __restrict__ bk,
    const float* __restrict__ wv, const float* __restrict__ bv,
    const float* __restrict__ wo, const float* __restrict__ bo,
    float* __restrict__ out)
{
    __shared__ int s_task;
    const int tid = threadIdx.x;

    // ---- phase 1: QKV tiles (my-major so early row-groups finish first) ----
    for (;;) {
        __syncthreads();
        if (tid == 0) s_task = atomicAdd(&g_ctr[0], 1);
        __syncthreads();
        const int t = s_task;
        if (t >= N_QKV) break;
        const int my = t / 24;
        const int z  = (t / 8) % 3;
        const int nx = t & 7;
        const float* B; const float* bias; float* C;
        if (z == 0)      { B = wq; bias = bq; C = g_q; }
        else if (z == 1) { B = wk; bias = bk; C = g_k; }
        else             { B = wv; bias = bv; C = g_v; }
        gemm_tc_body<4>(x, B, bias, C, my * BM, nx * 128);
        __syncthreads();
        if (tid == 0) {
            __threadfence();
            atomicExch(&g_flags[z * 128 + my * 8 + nx], 1);
        }
    }

    // ---- phase 2: attention blocks (row-group-major) ----
    for (;;) {
        __syncthreads();
        if (tid == 0) s_task = atomicAdd(&g_ctr[1], 1);
        __syncthreads();
        const int a = s_task;
        if (a >= N_ATT) break;
        const int rg = a >> 6;               // output row-group 0..15
        const int j  = a & 63;
        const int n  = rg >> 3;
        const int tb = (rg & 7) * 4 + (j >> 4);
        const int h  = j & 15;
        const int nh = n * 16 + h;
        if (tid == 0) {
            const int nt  = h >> 1;          // 128-col tile containing head h
            const int lo  = max(32 * tb - 64, 0);
            const int hi  = min(32 * tb + 95, TT - 1);
            const int mlo = n * 8 + lo / 128;
            const int mhi = n * 8 + hi / 128;
            spin_flag(&g_flags[0 * 128 + rg  * 8 + nt]);
            spin_flag(&g_flags[1 * 128 + mlo * 8 + nt]);
            spin_flag(&g_flags[1 * 128 + mhi * 8 + nt]);
            spin_flag(&g_flags[2 * 128 + mlo * 8 + nt]);
            spin_flag(&g_flags[2 * 128 + mhi * 8 + nt]);
            __threadfence();
        }
        __syncthreads();
        attn_body(tb, nh);
        __syncthreads();
        if (tid == 0) {
            __threadfence();
            atomicAdd(&g_rowcnt[rg], 1);
        }
    }

    // ---- phase 3: out-projection 128x64 tiles (my-major; ready-first) ----
    for (;;) {
        __syncthreads();
        if (tid == 0) s_task = atomicAdd(&g_ctr[2], 1);
        __syncthreads();
        const int o = s_task;
        if (o >= N_OUT) break;
        const int my = o >> 4;
        const int nx = o & 15;
        if (tid == 0) {
            while (atomicAdd(&g_rowcnt[my], 0) < 64) __nanosleep(256);
            __threadfence();
        }
        __syncthreads();
        gemm_tc_body<2>(g_attn, wo, bo, out, my * BM, nx * 64);
    }
}

// ---------------- launch ----------------
extern "C" void kernel_launch(void* const* d_in, const int* in_sizes, int n_in,
                              void* d_out, int out_size)
{
    const float* x  = (const float*)d_in[0];
    const float* wq = (const float*)d_in[1];
    const float* bq = (const float*)d_in[2];
    const float* wk = (const float*)d_in[3];
    const float* bk = (const float*)d_in[4];
    const float* wv = (const float*)d_in[5];
    const float* bv = (const float*)d_in[6];
    const float* wo = (const float*)d_in[7];
    const float* bo = (const float*)d_in[8];

    cudaFuncSetAttribute(fused_kernel,
                         cudaFuncAttributeMaxDynamicSharedMemorySize,
                         FUSED_SMEM_BYTES);

    reset_kernel<<<1, 512>>>();
    fused_kernel<<<GRID_P, 256, FUSED_SMEM_BYTES>>>(
        x, wq, bq, wk, bk, wv, bv, wo, bo, (float*)d_out);
}